// round 14
// baseline (speedup 1.0000x reference)
#include <cuda_runtime.h>
#include <cuda_fp16.h>
#include <cstdint>

// Problem constants
constexpr int SEQ = 2048;
constexpr int NB  = 2;      // batch
constexpr int CH  = 1024;   // channels
constexpr int NH  = 16;     // heads
constexpr int EPQ = 32;     // edges per query
constexpr int MROWS = SEQ * NB;         // 4096 GEMM rows
constexpr int QKV_N = 3 * CH;           // 3072 fused projection cols
constexpr int ATT_BLOCKS = SEQ * NB;    // 4096 (block per (query, b))

// GEMM smem geometry: 3 stages x (A + B) x 128 rows x 72 halves
constexpr int GBK = 64;                          // K per stage (128B rows)
constexpr int GST = 72;                          // 64 + 8 pad halves (144B stride)
constexpr uint32_t BUFB = 128 * GST * 2;         // 18,432 B per operand-stage
constexpr int GEMM_SMEM = 3 * 2 * (int)BUFB;     // 110,592 B (dynamic)

// -------- device scratch (no allocations allowed) --------
__device__ __half g_qkvh[MROWS * QKV_N];  // q | k | v per row (fp16)
__device__ __half g_attn[MROWS * CH];     // attention output (fp16)
__device__ __half g_xh[MROWS * CH];       // fp16 x
__device__ __half g_wh[4 * CH * CH];      // fp16 Wq|Wk|Wv|Wx

__device__ __forceinline__ void cp_async16(uint32_t sptr, const void* gptr) {
    asm volatile("cp.async.cg.shared.global [%0], [%1], 16;" :: "r"(sptr), "l"(gptr));
}
__device__ __forceinline__ void ldsm_x4(uint32_t addr, uint32_t& r0, uint32_t& r1,
                                        uint32_t& r2, uint32_t& r3) {
    asm volatile("ldmatrix.sync.aligned.m8n8.x4.shared.b16 {%0,%1,%2,%3}, [%4];"
                 : "=r"(r0), "=r"(r1), "=r"(r2), "=r"(r3) : "r"(addr));
}

// ============================================================
// single fused fp32 -> fp16 conversion pre-pass:
// chunks [0, 2^20) = x ; [2^20, 2^21) = Wq|Wk|Wv|Wx (2^18 each)
// ============================================================
constexpr int WSZ = CH * CH;            // 1,048,576
constexpr int XN4 = MROWS * CH / 4;     // 2^20
constexpr int WN4 = WSZ / 4;            // 2^18
constexpr int CVT_CHUNKS = XN4 + 4 * WN4;   // 2^21

__global__ __launch_bounds__(256) void cvt_all_kernel(
    const float4* __restrict__ x,
    const float4* __restrict__ wq, const float4* __restrict__ wk,
    const float4* __restrict__ wv, const float4* __restrict__ wx,
    __half2* __restrict__ xh, __half2* __restrict__ wh)
{
    const int i = blockIdx.x * 256 + threadIdx.x;
    const float4* src;
    __half2* dst;
    if (i < XN4) {
        src = x + i;
        dst = xh + 2 * (size_t)i;
    } else {
        const int j = i - XN4;
        const int sel = j >> 18;
        const int off = j & (WN4 - 1);
        const float4* w = sel == 0 ? wq : (sel == 1 ? wk : (sel == 2 ? wv : wx));
        src = w + off;
        dst = wh + 2 * ((size_t)sel * WN4 + off);
    }
    float4 v = *src;
    dst[0] = __floats2half2_rn(v.x, v.y);
    dst[1] = __floats2half2_rn(v.z, v.w);
}

// ============================================================
// FP16 tensor-core GEMM with bias (fp32 accum).
//   out[m,n] = sum_k A[m,k] * Wsel[nmod,k] + bsel[nmod]
// 128x128x64 tile; FOUR fat warps (2x2, warp tile 64x64, 32
// independent MMA per kstep per warp -> ILP fills the tensor
// pipe from a single warp). THREE-stage cp.async pipeline,
// prefetch distance 3. mma.sync.m16n8k16.f16, smem row stride
// 72 halves (144B, ldsm conflict-free). DYNAMIC smem 110,592 B.
// 2 CTAs/SM (8 warps, ~220 regs/thread under the 256 cap).
// OUT = __half (qkv) or float (final out).
// ============================================================
template <typename OUT>
__global__ __launch_bounds__(128, 2) void hgemm_bias_kernel(
    const __half* __restrict__ A,
    const __half* __restrict__ W0, const __half* __restrict__ W1,
    const __half* __restrict__ W2,
    const float* __restrict__ b0, const float* __restrict__ b1,
    const float* __restrict__ b2,
    OUT* __restrict__ out, int N, int K)
{
    extern __shared__ __half smem[];
    const uint32_t sAs = (uint32_t)__cvta_generic_to_shared(smem);   // 3 A stages
    const uint32_t sBs = sAs + 3 * BUFB;                             // 3 B stages

    const int bm = blockIdx.y * 128;
    const int bn = blockIdx.x * 128;
    const int sel = bn >> 10;
    const __half* W = sel == 0 ? W0 : (sel == 1 ? W1 : W2);
    const float* bias = sel == 0 ? b0 : (sel == 1 ? b1 : b2);
    const int wbase = bn & 1023;

    const int t    = threadIdx.x;
    const int lane = t & 31;
    const int warp = t >> 5;              // 0..3
    const int gid  = lane >> 2;
    const int tig  = lane & 3;
    const int wm = (warp >> 1) * 64;      // 2 warps in m
    const int wn = (warp & 1) * 64;       // 2 warps in n

    const int lrow16 = lane & 15;
    const int lc8    = (lane >> 4) * 8;

    float c[4][8][4];
    #pragma unroll
    for (int mi = 0; mi < 4; mi++)
        #pragma unroll
        for (int ni = 0; ni < 8; ni++)
            #pragma unroll
            for (int r = 0; r < 4; r++) c[mi][ni][r] = 0.0f;

    // stage copy: 128 rows x 64 halves (128B) per operand =
    // 1024 16B chunks; 8 chunks per thread per operand
    auto issue = [&](int k0, int st) {
        #pragma unroll
        for (int i = 0; i < 8; i++) {
            const int ch = t + i * 128;          // 0..1023
            const int row = ch >> 3, c8 = (ch & 7) * 8;
            cp_async16(sAs + st * BUFB + (row * GST + c8) * 2,
                       A + (size_t)(bm + row) * K + k0 + c8);
            cp_async16(sBs + st * BUFB + (row * GST + c8) * 2,
                       W + (size_t)(wbase + row) * K + k0 + c8);
        }
        asm volatile("cp.async.commit_group;");
    };

    // fragment load for one kstep (16 wide): 4 A frags + 8 B groups
    auto load_frags = [&](uint32_t aB, uint32_t bB, int ks,
                          uint32_t a[4][4], uint32_t b[8][2]) {
        #pragma unroll
        for (int mi = 0; mi < 4; mi++)
            ldsm_x4(aB + ((wm + mi * 16 + lrow16) * GST + ks + lc8) * 2,
                    a[mi][0], a[mi][1], a[mi][2], a[mi][3]);
        #pragma unroll
        for (int ni2 = 0; ni2 < 4; ni2++) {
            uint32_t r0, r1, r2, r3;
            ldsm_x4(bB + ((wn + ni2 * 16 + lrow16) * GST + ks + lc8) * 2,
                    r0, r1, r2, r3);
            b[2 * ni2][0] = r0;      b[2 * ni2][1] = r2;
            b[2 * ni2 + 1][0] = r1;  b[2 * ni2 + 1][1] = r3;
        }
    };
    auto do_mma = [&](uint32_t a[4][4], uint32_t b[8][2]) {
        #pragma unroll
        for (int ni = 0; ni < 8; ni++)
            #pragma unroll
            for (int mi = 0; mi < 4; mi++) {
                asm volatile(
                    "mma.sync.aligned.m16n8k16.row.col.f32.f16.f16.f32 "
                    "{%0,%1,%2,%3}, {%4,%5,%6,%7}, {%8,%9}, {%0,%1,%2,%3};"
                    : "+f"(c[mi][ni][0]), "+f"(c[mi][ni][1]),
                      "+f"(c[mi][ni][2]), "+f"(c[mi][ni][3])
                    : "r"(a[mi][0]), "r"(a[mi][1]), "r"(a[mi][2]), "r"(a[mi][3]),
                      "r"(b[ni][0]), "r"(b[ni][1]));
            }
    };

    const int NSTEP = K / GBK;                 // 16
    issue(0 * GBK, 0);
    issue(1 * GBK, 1);
    issue(2 * GBK, 2);

    for (int s = 0; s < NSTEP; s++) {
        const int buf = s % 3;
        if (s + 3 <= NSTEP)      asm volatile("cp.async.wait_group 2;");
        else if (s + 2 == NSTEP) asm volatile("cp.async.wait_group 1;");
        else                     asm volatile("cp.async.wait_group 0;");
        __syncthreads();

        const uint32_t aB = sAs + buf * BUFB;
        const uint32_t bB = sBs + buf * BUFB;

        // software-pipelined ksteps: load next frags during mma
        uint32_t a0[4][4], b0r[8][2], a1[4][4], b1r[8][2];
        load_frags(aB, bB, 0, a0, b0r);
        load_frags(aB, bB, 16, a1, b1r);
        do_mma(a0, b0r);
        load_frags(aB, bB, 32, a0, b0r);
        do_mma(a1, b1r);
        load_frags(aB, bB, 48, a1, b1r);
        do_mma(a0, b0r);
        do_mma(a1, b1r);

        __syncthreads();            // all warps done reading buf
        if (s + 3 < NSTEP) issue((s + 3) * GBK, buf);
    }

    #pragma unroll
    for (int mi = 0; mi < 4; mi++) {
        const int row = bm + wm + mi * 16 + gid;
        #pragma unroll
        for (int ni = 0; ni < 8; ni++) {
            const int col = bn + wn + ni * 8 + tig * 2;
            const float2 bv = *(const float2*)(bias + (wbase + wn + ni * 8 + tig * 2));
            const float o0 = c[mi][ni][0] + bv.x, o1 = c[mi][ni][1] + bv.y;
            const float o2 = c[mi][ni][2] + bv.x, o3 = c[mi][ni][3] + bv.y;
            if constexpr (sizeof(OUT) == 2) {
                *(__half2*)((__half*)out + (size_t)row * N + col) =
                    __floats2half2_rn(o0, o1);
                *(__half2*)((__half*)out + (size_t)(row + 8) * N + col) =
                    __floats2half2_rn(o2, o3);
            } else {
                *(float2*)((float*)out + (size_t)row * N + col) = make_float2(o0, o1);
                *(float2*)((float*)out + (size_t)(row + 8) * N + col) = make_float2(o2, o3);
            }
        }
    }
}

// ============================================================
// FUSED sparse attention: block per (query s, b).
// num/d invariant to softmax shift -> per-(s,b,h) local max,
// no global reduction. Phases: dots -> max/exp/denom -> V sweep.
// q_id = repeat(arange(S), EPQ) -> query = e >> 5.
// ============================================================
__global__ __launch_bounds__(256) void fused_attn_kernel(
    const __half* __restrict__ qkv, const int* __restrict__ k_id,
    __half* __restrict__ attn)
{
    __shared__ uint4 qrow[CH / 8];
    __shared__ float sw[EPQ * NH];
    __shared__ float smax[NH];
    __shared__ float sinvd[NH];
    __shared__ int ksm[EPQ];

    const int s = blockIdx.x >> 1;
    const int b = blockIdx.x & 1;
    const int t    = threadIdx.x;
    const int lane = t & 31;
    const int warp = t >> 5;
    const int ebase = s * EPQ;

    if (t < CH / 8)
        qrow[t] = *((const uint4*)(qkv + (size_t)(s * NB + b) * QKV_N) + t);
    if (t < EPQ) ksm[t] = k_id[ebase + t];
    __syncthreads();

    #pragma unroll
    for (int i = 0; i < 4; i++) {
        const int e = warp * 4 + i;
        const uint4* kp = (const uint4*)(
            qkv + (size_t)(ksm[e] * NB + b) * QKV_N + CH);
        #pragma unroll
        for (int it = 0; it < 4; it++) {
            const uint4 qa = qrow[it * 32 + lane];
            const uint4 ka = kp[it * 32 + lane];
            float p = 0.0f;
            {
                const __half2* qh = (const __half2*)&qa;
                const __half2* kh = (const __half2*)&ka;
                #pragma unroll
                for (int u = 0; u < 4; u++) {
                    const float2 qf = __half22float2(qh[u]);
                    const float2 kf = __half22float2(kh[u]);
                    p += qf.x * kf.x + qf.y * kf.y;
                }
            }
            p += __shfl_xor_sync(0xffffffffu, p, 1);
            p += __shfl_xor_sync(0xffffffffu, p, 2);
            p += __shfl_xor_sync(0xffffffffu, p, 4);
            if ((lane & 7) == 0)
                sw[e * NH + it * 4 + (lane >> 3)] = p * 0.125f;
        }
    }
    __syncthreads();

    if (t < NH) {
        float m = sw[t];
        #pragma unroll
        for (int e = 1; e < EPQ; e++) m = fmaxf(m, sw[e * NH + t]);
        smax[t] = m;
    }
    __syncthreads();
    #pragma unroll
    for (int i = 0; i < 2; i++) {
        const int idx = t + i * 256;
        sw[idx] = expf(sw[idx] - smax[idx & 15]);
    }
    __syncthreads();
    if (t < NH) {
        float d = 0.0f;
        #pragma unroll
        for (int e = 0; e < EPQ; e++) d += sw[e * NH + t];
        sinvd[t] = 1.0f / d;
    }
    __syncthreads();

    const int h = t >> 4;
    float4 acc = make_float4(0.f, 0.f, 0.f, 0.f);
    #pragma unroll 4
    for (int e = 0; e < EPQ; e++) {
        const float w = sw[e * NH + h];
        const uint2 vr = *((const uint2*)(
            qkv + (size_t)(ksm[e] * NB + b) * QKV_N + 2 * CH) + t);
        const float2 v0 = __half22float2(*(const __half2*)&vr.x);
        const float2 v1 = __half22float2(*(const __half2*)&vr.y);
        acc.x += w * v0.x; acc.y += w * v0.y;
        acc.z += w * v1.x; acc.w += w * v1.y;
    }
    const float inv = sinvd[h];
    __half2* op = (__half2*)(attn + (size_t)(s * NB + b) * CH) + 2 * t;
    op[0] = __floats2half2_rn(acc.x * inv, acc.y * inv);
    op[1] = __floats2half2_rn(acc.z * inv, acc.w * inv);
}

// ============================================================
// host launcher (graph-capturable: kernel launches only)
// ============================================================
extern "C" void kernel_launch(void* const* d_in, const int* in_sizes, int n_in,
                              void* d_out, int out_size)
{
    const float* x   = (const float*)d_in[0];
    const int*  k_id = (const int*)d_in[2];
    const float* Wq  = (const float*)d_in[3];
    const float* bq  = (const float*)d_in[4];
    const float* Wk  = (const float*)d_in[5];
    const float* bk  = (const float*)d_in[6];
    const float* Wv  = (const float*)d_in[7];
    const float* bv  = (const float*)d_in[8];
    const float* Wx  = (const float*)d_in[9];
    const float* bx  = (const float*)d_in[10];
    float* out = (float*)d_out;

    __half *qkvh, *attn, *xh, *wh;
    cudaGetSymbolAddress((void**)&qkvh, g_qkvh);
    cudaGetSymbolAddress((void**)&attn, g_attn);
    cudaGetSymbolAddress((void**)&xh,   g_xh);
    cudaGetSymbolAddress((void**)&wh,   g_wh);

    // idempotent host-side attribute set (no device state, capture-legal)
    cudaFuncSetAttribute(hgemm_bias_kernel<__half>,
                         cudaFuncAttributeMaxDynamicSharedMemorySize, GEMM_SMEM);
    cudaFuncSetAttribute(hgemm_bias_kernel<float>,
                         cudaFuncAttributeMaxDynamicSharedMemorySize, GEMM_SMEM);

    // fused fp16 conversion pre-pass
    cvt_all_kernel<<<CVT_CHUNKS / 256, 256>>>(
        (const float4*)x, (const float4*)Wq, (const float4*)Wk,
        (const float4*)Wv, (const float4*)Wx, (__half2*)xh, (__half2*)wh);

    // fused q/k/v projection: one GEMM, N=3072, fp16 output
    hgemm_bias_kernel<__half><<<dim3(QKV_N / 128, MROWS / 128), 128, GEMM_SMEM>>>(
        xh, wh + 0 * WSZ, wh + 1 * WSZ, wh + 2 * WSZ, bq, bk, bv, qkvh, QKV_N, CH);

    // fused edge dots + local-max softmax + V aggregation
    fused_attn_kernel<<<ATT_BLOCKS, 256>>>(qkvh, k_id, attn);

    // output projection, fp32 output
    hgemm_bias_kernel<float><<<dim3(CH / 128, MROWS / 128), 128, GEMM_SMEM>>>(
        attn, wh + 3 * WSZ, wh + 3 * WSZ, wh + 3 * WSZ, bx, bx, bx, out, CH, CH);
}

// round 15
// speedup vs baseline: 1.0080x; 1.0080x over previous
#include <cuda_runtime.h>
#include <cuda_fp16.h>
#include <cstdint>

// Problem constants
constexpr int SEQ = 2048;
constexpr int NB  = 2;      // batch
constexpr int CH  = 1024;   // channels
constexpr int NH  = 16;     // heads
constexpr int EPQ = 32;     // edges per query
constexpr int MROWS = SEQ * NB;         // 4096 GEMM rows
constexpr int QKV_N = 3 * CH;           // 3072 fused projection cols
constexpr int ATT_BLOCKS = SEQ * NB;    // 4096 (block per (query, b))

// GEMM smem geometry: 3 stages x (A + B) x 128 rows x 72 halves
constexpr int GBK = 64;                          // K per stage (128B rows)
constexpr int GST = 72;                          // 64 + 8 pad halves (144B stride)
constexpr uint32_t BUFB = 128 * GST * 2;         // 18,432 B per operand-stage
constexpr int GEMM_SMEM = 3 * 2 * (int)BUFB;     // 110,592 B (dynamic)

// -------- device scratch (no allocations allowed) --------
__device__ __half g_qkvh[MROWS * QKV_N];  // q | k | v per row (fp16)
__device__ __half g_attn[MROWS * CH];     // attention output (fp16)
__device__ __half g_xh[MROWS * CH];       // fp16 x
__device__ __half g_wh[4 * CH * CH];      // fp16 Wq|Wk|Wv|Wx

__device__ __forceinline__ void cp_async16(uint32_t sptr, const void* gptr) {
    asm volatile("cp.async.cg.shared.global [%0], [%1], 16;" :: "r"(sptr), "l"(gptr));
}
__device__ __forceinline__ void ldsm_x4(uint32_t addr, uint32_t& r0, uint32_t& r1,
                                        uint32_t& r2, uint32_t& r3) {
    asm volatile("ldmatrix.sync.aligned.m8n8.x4.shared.b16 {%0,%1,%2,%3}, [%4];"
                 : "=r"(r0), "=r"(r1), "=r"(r2), "=r"(r3) : "r"(addr));
}

// ============================================================
// single fused fp32 -> fp16 conversion pre-pass:
// chunks [0, 2^20) = x ; [2^20, 2^21) = Wq|Wk|Wv|Wx (2^18 each)
// 4 independent chunks per thread (MLP=4) to hide DRAM latency.
// ============================================================
constexpr int WSZ = CH * CH;            // 1,048,576
constexpr int XN4 = MROWS * CH / 4;     // 2^20
constexpr int WN4 = WSZ / 4;            // 2^18
constexpr int CVT_CHUNKS = XN4 + 4 * WN4;   // 2^21
constexpr int CVT_BLOCKS = CVT_CHUNKS / 1024; // 2048 (4 chunks/thread)

__global__ __launch_bounds__(256) void cvt_all_kernel(
    const float4* __restrict__ x,
    const float4* __restrict__ wq, const float4* __restrict__ wk,
    const float4* __restrict__ wv, const float4* __restrict__ wx,
    __half2* __restrict__ xh, __half2* __restrict__ wh)
{
    const int base = blockIdx.x * 1024 + threadIdx.x;
    float4 v[4];
    __half2* dst[4];
    #pragma unroll
    for (int j = 0; j < 4; j++) {
        const int i = base + j * 256;
        const float4* src;
        if (i < XN4) {
            src = x + i;
            dst[j] = xh + 2 * (size_t)i;
        } else {
            const int k = i - XN4;
            const int sel = k >> 18;
            const int off = k & (WN4 - 1);
            const float4* w = sel == 0 ? wq : (sel == 1 ? wk : (sel == 2 ? wv : wx));
            src = w + off;
            dst[j] = wh + 2 * ((size_t)sel * WN4 + off);
        }
        v[j] = *src;                       // 4 independent loads in flight
    }
    #pragma unroll
    for (int j = 0; j < 4; j++) {
        dst[j][0] = __floats2half2_rn(v[j].x, v[j].y);
        dst[j][1] = __floats2half2_rn(v[j].z, v[j].w);
    }
}

// ============================================================
// FP16 tensor-core GEMM with bias (fp32 accum) — R13 config
// (measured best; mma.sync rate ceiling reached, do not touch).
//   out[m,n] = sum_k A[m,k] * Wsel[nmod,k] + bsel[nmod]
// 128x128x64 tile; THREE-stage cp.async pipeline, prefetch
// distance 3. 8 warps 4x2 (warp tile 32x64), fragment-level
// ldsm/mma double buffering, mma.sync.m16n8k16.f16, smem row
// stride 72 halves. DYNAMIC smem 110,592 B. 2 CTAs/SM.
// OUT = __half (qkv) or float (final out).
// ============================================================
template <typename OUT>
__global__ __launch_bounds__(256, 2) void hgemm_bias_kernel(
    const __half* __restrict__ A,
    const __half* __restrict__ W0, const __half* __restrict__ W1,
    const __half* __restrict__ W2,
    const float* __restrict__ b0, const float* __restrict__ b1,
    const float* __restrict__ b2,
    OUT* __restrict__ out, int N, int K)
{
    extern __shared__ __half smem[];
    const uint32_t sAs = (uint32_t)__cvta_generic_to_shared(smem);   // 3 A stages
    const uint32_t sBs = sAs + 3 * BUFB;                             // 3 B stages

    const int bm = blockIdx.y * 128;
    const int bn = blockIdx.x * 128;
    const int sel = bn >> 10;
    const __half* W = sel == 0 ? W0 : (sel == 1 ? W1 : W2);
    const float* bias = sel == 0 ? b0 : (sel == 1 ? b1 : b2);
    const int wbase = bn & 1023;

    const int t    = threadIdx.x;
    const int lane = t & 31;
    const int warp = t >> 5;
    const int gid  = lane >> 2;
    const int tig  = lane & 3;
    const int wm = (warp >> 1) * 32;
    const int wn = (warp & 1) * 64;

    const int lrow16 = lane & 15;
    const int lc8    = (lane >> 4) * 8;

    float c[2][8][4];
    #pragma unroll
    for (int mi = 0; mi < 2; mi++)
        #pragma unroll
        for (int ni = 0; ni < 8; ni++)
            #pragma unroll
            for (int r = 0; r < 4; r++) c[mi][ni][r] = 0.0f;

    auto issue = [&](int k0, int st) {
        #pragma unroll
        for (int i = 0; i < 4; i++) {
            const int ch = t + i * 256;          // 0..1023
            const int row = ch >> 3, c8 = (ch & 7) * 8;
            cp_async16(sAs + st * BUFB + (row * GST + c8) * 2,
                       A + (size_t)(bm + row) * K + k0 + c8);
            cp_async16(sBs + st * BUFB + (row * GST + c8) * 2,
                       W + (size_t)(wbase + row) * K + k0 + c8);
        }
        asm volatile("cp.async.commit_group;");
    };

    auto load_frags = [&](uint32_t aB, uint32_t bB, int ks,
                          uint32_t a[2][4], uint32_t b[8][2]) {
        #pragma unroll
        for (int mi = 0; mi < 2; mi++)
            ldsm_x4(aB + ((wm + mi * 16 + lrow16) * GST + ks + lc8) * 2,
                    a[mi][0], a[mi][1], a[mi][2], a[mi][3]);
        #pragma unroll
        for (int ni2 = 0; ni2 < 4; ni2++) {
            uint32_t r0, r1, r2, r3;
            ldsm_x4(bB + ((wn + ni2 * 16 + lrow16) * GST + ks + lc8) * 2,
                    r0, r1, r2, r3);
            b[2 * ni2][0] = r0;      b[2 * ni2][1] = r2;
            b[2 * ni2 + 1][0] = r1;  b[2 * ni2 + 1][1] = r3;
        }
    };
    auto do_mma = [&](uint32_t a[2][4], uint32_t b[8][2]) {
        #pragma unroll
        for (int ni = 0; ni < 8; ni++)
            #pragma unroll
            for (int mi = 0; mi < 2; mi++) {
                asm volatile(
                    "mma.sync.aligned.m16n8k16.row.col.f32.f16.f16.f32 "
                    "{%0,%1,%2,%3}, {%4,%5,%6,%7}, {%8,%9}, {%0,%1,%2,%3};"
                    : "+f"(c[mi][ni][0]), "+f"(c[mi][ni][1]),
                      "+f"(c[mi][ni][2]), "+f"(c[mi][ni][3])
                    : "r"(a[mi][0]), "r"(a[mi][1]), "r"(a[mi][2]), "r"(a[mi][3]),
                      "r"(b[ni][0]), "r"(b[ni][1]));
            }
    };

    const int NSTEP = K / GBK;                 // 16
    issue(0 * GBK, 0);
    issue(1 * GBK, 1);
    issue(2 * GBK, 2);

    for (int s = 0; s < NSTEP; s++) {
        const int buf = s % 3;
        if (s + 3 <= NSTEP)      asm volatile("cp.async.wait_group 2;");
        else if (s + 2 == NSTEP) asm volatile("cp.async.wait_group 1;");
        else                     asm volatile("cp.async.wait_group 0;");
        __syncthreads();

        const uint32_t aB = sAs + buf * BUFB;
        const uint32_t bB = sBs + buf * BUFB;

        uint32_t a0[2][4], b0r[8][2], a1[2][4], b1r[8][2];
        load_frags(aB, bB, 0, a0, b0r);
        load_frags(aB, bB, 16, a1, b1r);
        do_mma(a0, b0r);
        load_frags(aB, bB, 32, a0, b0r);
        do_mma(a1, b1r);
        load_frags(aB, bB, 48, a1, b1r);
        do_mma(a0, b0r);
        do_mma(a1, b1r);

        __syncthreads();
        if (s + 3 < NSTEP) issue((s + 3) * GBK, buf);
    }

    #pragma unroll
    for (int mi = 0; mi < 2; mi++) {
        const int row = bm + wm + mi * 16 + gid;
        #pragma unroll
        for (int ni = 0; ni < 8; ni++) {
            const int col = bn + wn + ni * 8 + tig * 2;
            const float2 bv = *(const float2*)(bias + (wbase + wn + ni * 8 + tig * 2));
            const float o0 = c[mi][ni][0] + bv.x, o1 = c[mi][ni][1] + bv.y;
            const float o2 = c[mi][ni][2] + bv.x, o3 = c[mi][ni][3] + bv.y;
            if constexpr (sizeof(OUT) == 2) {
                *(__half2*)((__half*)out + (size_t)row * N + col) =
                    __floats2half2_rn(o0, o1);
                *(__half2*)((__half*)out + (size_t)(row + 8) * N + col) =
                    __floats2half2_rn(o2, o3);
            } else {
                *(float2*)((float*)out + (size_t)row * N + col) = make_float2(o0, o1);
                *(float2*)((float*)out + (size_t)(row + 8) * N + col) = make_float2(o2, o3);
            }
        }
    }
}

// ============================================================
// FUSED sparse attention: block per (query s, b) — at its L2
// bandwidth floor (~44us for 532MB of L2-resident gathers).
// num/d invariant to softmax shift -> per-(s,b,h) local max.
// q_id = repeat(arange(S), EPQ) -> query = e >> 5.
// ============================================================
__global__ __launch_bounds__(256) void fused_attn_kernel(
    const __half* __restrict__ qkv, const int* __restrict__ k_id,
    __half* __restrict__ attn)
{
    __shared__ uint4 qrow[CH / 8];
    __shared__ float sw[EPQ * NH];
    __shared__ float smax[NH];
    __shared__ float sinvd[NH];
    __shared__ int ksm[EPQ];

    const int s = blockIdx.x >> 1;
    const int b = blockIdx.x & 1;
    const int t    = threadIdx.x;
    const int lane = t & 31;
    const int warp = t >> 5;
    const int ebase = s * EPQ;

    if (t < CH / 8)
        qrow[t] = *((const uint4*)(qkv + (size_t)(s * NB + b) * QKV_N) + t);
    if (t < EPQ) ksm[t] = k_id[ebase + t];
    __syncthreads();

    #pragma unroll
    for (int i = 0; i < 4; i++) {
        const int e = warp * 4 + i;
        const uint4* kp = (const uint4*)(
            qkv + (size_t)(ksm[e] * NB + b) * QKV_N + CH);
        #pragma unroll
        for (int it = 0; it < 4; it++) {
            const uint4 qa = qrow[it * 32 + lane];
            const uint4 ka = kp[it * 32 + lane];
            float p = 0.0f;
            {
                const __half2* qh = (const __half2*)&qa;
                const __half2* kh = (const __half2*)&ka;
                #pragma unroll
                for (int u = 0; u < 4; u++) {
                    const float2 qf = __half22float2(qh[u]);
                    const float2 kf = __half22float2(kh[u]);
                    p += qf.x * kf.x + qf.y * kf.y;
                }
            }
            p += __shfl_xor_sync(0xffffffffu, p, 1);
            p += __shfl_xor_sync(0xffffffffu, p, 2);
            p += __shfl_xor_sync(0xffffffffu, p, 4);
            if ((lane & 7) == 0)
                sw[e * NH + it * 4 + (lane >> 3)] = p * 0.125f;
        }
    }
    __syncthreads();

    if (t < NH) {
        float m = sw[t];
        #pragma unroll
        for (int e = 1; e < EPQ; e++) m = fmaxf(m, sw[e * NH + t]);
        smax[t] = m;
    }
    __syncthreads();
    #pragma unroll
    for (int i = 0; i < 2; i++) {
        const int idx = t + i * 256;
        sw[idx] = expf(sw[idx] - smax[idx & 15]);
    }
    __syncthreads();
    if (t < NH) {
        float d = 0.0f;
        #pragma unroll
        for (int e = 0; e < EPQ; e++) d += sw[e * NH + t];
        sinvd[t] = 1.0f / d;
    }
    __syncthreads();

    const int h = t >> 4;
    float4 acc = make_float4(0.f, 0.f, 0.f, 0.f);
    #pragma unroll 4
    for (int e = 0; e < EPQ; e++) {
        const float w = sw[e * NH + h];
        const uint2 vr = *((const uint2*)(
            qkv + (size_t)(ksm[e] * NB + b) * QKV_N + 2 * CH) + t);
        const float2 v0 = __half22float2(*(const __half2*)&vr.x);
        const float2 v1 = __half22float2(*(const __half2*)&vr.y);
        acc.x += w * v0.x; acc.y += w * v0.y;
        acc.z += w * v1.x; acc.w += w * v1.y;
    }
    const float inv = sinvd[h];
    __half2* op = (__half2*)(attn + (size_t)(s * NB + b) * CH) + 2 * t;
    op[0] = __floats2half2_rn(acc.x * inv, acc.y * inv);
    op[1] = __floats2half2_rn(acc.z * inv, acc.w * inv);
}

// ============================================================
// host launcher (graph-capturable: kernel launches only)
// ============================================================
extern "C" void kernel_launch(void* const* d_in, const int* in_sizes, int n_in,
                              void* d_out, int out_size)
{
    const float* x   = (const float*)d_in[0];
    const int*  k_id = (const int*)d_in[2];
    const float* Wq  = (const float*)d_in[3];
    const float* bq  = (const float*)d_in[4];
    const float* Wk  = (const float*)d_in[5];
    const float* bk  = (const float*)d_in[6];
    const float* Wv  = (const float*)d_in[7];
    const float* bv  = (const float*)d_in[8];
    const float* Wx  = (const float*)d_in[9];
    const float* bx  = (const float*)d_in[10];
    float* out = (float*)d_out;

    __half *qkvh, *attn, *xh, *wh;
    cudaGetSymbolAddress((void**)&qkvh, g_qkvh);
    cudaGetSymbolAddress((void**)&attn, g_attn);
    cudaGetSymbolAddress((void**)&xh,   g_xh);
    cudaGetSymbolAddress((void**)&wh,   g_wh);

    // idempotent host-side attribute set (no device state, capture-legal)
    cudaFuncSetAttribute(hgemm_bias_kernel<__half>,
                         cudaFuncAttributeMaxDynamicSharedMemorySize, GEMM_SMEM);
    cudaFuncSetAttribute(hgemm_bias_kernel<float>,
                         cudaFuncAttributeMaxDynamicSharedMemorySize, GEMM_SMEM);

    // fused fp16 conversion pre-pass (4 chunks/thread, MLP=4)
    cvt_all_kernel<<<CVT_BLOCKS, 256>>>(
        (const float4*)x, (const float4*)Wq, (const float4*)Wk,
        (const float4*)Wv, (const float4*)Wx, (__half2*)xh, (__half2*)wh);

    // fused q/k/v projection: one GEMM, N=3072, fp16 output
    hgemm_bias_kernel<__half><<<dim3(QKV_N / 128, MROWS / 128), 256, GEMM_SMEM>>>(
        xh, wh + 0 * WSZ, wh + 1 * WSZ, wh + 2 * WSZ, bq, bk, bv, qkvh, QKV_N, CH);

    // fused edge dots + local-max softmax + V aggregation
    fused_attn_kernel<<<ATT_BLOCKS, 256>>>(qkvh, k_id, attn);

    // output projection, fp32 output
    hgemm_bias_kernel<float><<<dim3(CH / 128, MROWS / 128), 256, GEMM_SMEM>>>(
        attn, wh + 3 * WSZ, wh + 3 * WSZ, wh + 3 * WSZ, bx, bx, bx, out, CH, CH);
}